// round 17
// baseline (speedup 1.0000x reference)
#include <cuda_runtime.h>
#include <cuda_bf16.h>
#include <cstdint>

// Problem constants
#define BATCH 1024
#define NN    156
#define MT    160               // padded M tile
#define CIN   301
#define CH    128
#define EDGES 1564
#define ETOT  (EDGES + NN)      // 1720
#define MTOT  (BATCH * NN)
#define BN_INV_SQRT 0.9999950000374997f

#define NSLOT 9
#define CHUNK_ELEMS (128 * 64)   // bf16 per slot (per hi/lo)
#define AW 36                    // smem row stride, 32-bit words (BK=64)
#define AWB 144                  // bytes

// smem layout (bytes)
#define OFF_AH 0                 // 160*144 = 23040
#define OFF_AL 23040
#define OFF_BH 46080             // 128*144 = 18432
#define OFF_BL 64512
#define OFF_T  0                 // fp32 [156][132] = 82368 (overlays A/B)
#define OFF_EDG 82944            // int2[1720] = 13760
#define OFF_PTR 96704            // int[157]
#define SMEM_FUSED 97344

// ---------------- scratch (static device memory) ----------------------------
__device__ __nv_bfloat16 g_Hhi[(size_t)MTOT * CH];
__device__ __nv_bfloat16 g_Hlo[(size_t)MTOT * CH];
__device__ int   g_ptr[NN + 1];
__device__ int2  g_edge[ETOT];
__device__ __nv_bfloat16 g_WtHi[NSLOT * CHUNK_ELEMS];   // [slot][n][k]
__device__ __nv_bfloat16 g_WtLo[NSLOT * CHUNK_ELEMS];

// ---------------- helpers ----------------------------------------------------
__device__ __forceinline__ uint32_t bf16x2_pack(float lo_elem, float hi_elem) {
    uint32_t r;
    asm("cvt.rn.bf16x2.f32 %0, %1, %2;" : "=r"(r) : "f"(hi_elem), "f"(lo_elem));
    return r;
}
__device__ __forceinline__ void mma16816(float* c, const uint32_t* a,
                                         uint32_t b0, uint32_t b1) {
    asm volatile(
        "mma.sync.aligned.m16n8k16.row.col.f32.bf16.bf16.f32 "
        "{%0,%1,%2,%3}, {%4,%5,%6,%7}, {%8,%9}, {%0,%1,%2,%3};"
        : "+f"(c[0]), "+f"(c[1]), "+f"(c[2]), "+f"(c[3])
        : "r"(a[0]), "r"(a[1]), "r"(a[2]), "r"(a[3]), "r"(b0), "r"(b1));
}
__device__ __forceinline__ void ldsm_x4(uint32_t* r, uint32_t addr) {
    asm volatile(
        "ldmatrix.sync.aligned.m8n8.x4.shared.b16 {%0,%1,%2,%3}, [%4];"
        : "=r"(r[0]), "=r"(r[1]), "=r"(r[2]), "=r"(r[3]) : "r"(addr));
}
__device__ __forceinline__ uint32_t smem_u32(const void* p) {
    uint32_t a;
    asm("{ .reg .u64 t; cvta.to.shared.u64 t, %1; cvt.u32.u64 %0, t; }"
        : "=r"(a) : "l"(p));
    return a;
}
__device__ __forceinline__ void fma4(float4& a, float4 t, float m) {
    a.x = fmaf(t.x, m, a.x); a.y = fmaf(t.y, m, a.y);
    a.z = fmaf(t.z, m, a.z); a.w = fmaf(t.w, m, a.w);
}

// ---------------- kernel 1: graph preprocessing -> packed CSC ---------------
__global__ void build_kernel(const void* __restrict__ eiv) {
    const int* e32 = (const int*)eiv;
    __shared__ int   is64;
    __shared__ float deg[NN];
    __shared__ float dinv[NN];
    __shared__ int   cnt[NN];
    __shared__ int   base[NN + 1];
    int tid = threadIdx.x;

    if (tid == 0) {
        int all_zero = 1;
        for (int i = 1; i < 129; i += 2)
            if (e32[i] != 0) { all_zero = 0; break; }
        is64 = all_zero;
    }
    if (tid < NN) { deg[tid] = 1.0f; cnt[tid] = 1; }
    __syncthreads();

    const int stride64 = is64;
    auto fetch = [&](int i) -> int {
        int v = e32[i << stride64];
        return min(max(v, 0), NN - 1);
    };

    for (int e = tid; e < EDGES; e += blockDim.x) {
        int cl = fetch(EDGES + e);
        atomicAdd(&deg[cl], 1.0f);
        atomicAdd(&cnt[cl], 1);
    }
    __syncthreads();
    if (tid < NN) dinv[tid] = rsqrtf(deg[tid]);
    if (tid == 0) {
        int run = 0;
        for (int n = 0; n < NN; n++) { base[n] = run; run += cnt[n]; }
        base[NN] = run;
    }
    __syncthreads();
    if (tid <= NN) g_ptr[tid] = base[tid];
    if (tid < NN) cnt[tid] = base[tid];
    __syncthreads();

    for (int e = tid; e < EDGES; e += blockDim.x) {
        int r  = fetch(e);
        int cl = fetch(EDGES + e);
        int pos = atomicAdd(&cnt[cl], 1);
        g_edge[pos] = make_int2(r, __float_as_int(dinv[r] * dinv[cl]));
    }
    __syncthreads();
    for (int n = tid; n < NN; n += blockDim.x) {
        int pos = atomicAdd(&cnt[n], 1);
        g_edge[pos] = make_int2(n, __float_as_int(dinv[n] * dinv[n]));
    }
}

// ---------------- kernel 2: W prep: split + transpose ------------------------
__global__ void wprep_kernel(const float* __restrict__ W0,
                             const float* __restrict__ W1,
                             const float* __restrict__ W2) {
    int gid = blockIdx.x * blockDim.x + threadIdx.x;
    if (gid >= NSLOT * CHUNK_ELEMS) return;
    int slot = gid >> 13;
    int rem  = gid & 8191;
    int n = rem >> 6;
    int k = rem & 63;
    const float* W; int K; int c0;
    if (slot < 5)      { W = W0; K = CIN; c0 = slot; }
    else if (slot < 7) { W = W1; K = CH;  c0 = slot - 5; }
    else               { W = W2; K = CH;  c0 = slot - 7; }
    int kg = c0 * 64 + k;
    float v = (kg < K) ? W[(size_t)kg * CH + n] : 0.0f;
    __nv_bfloat16 hi = __float2bfloat16(v);
    __nv_bfloat16 lo = __float2bfloat16(v - __bfloat162float(hi));
    g_WtHi[gid] = hi;
    g_WtLo[gid] = lo;
}

// ---------------- fused kernel: per-batch GEMM + agg --------------------------
// AG:   A from fp32 global x (split on the fly).  else: A copied from g_Hhi/lo.
// LAST: agg writes fp32 to out.                   else: BN+ReLU, bf16 hi/lo.
template<bool AG, bool LAST>
__global__ void __launch_bounds__(256, 2) fused_layer(
    const float* __restrict__ xA, int K, int nchunks,
    const __nv_bfloat16* __restrict__ aHi,
    const __nv_bfloat16* __restrict__ aLo,
    const __nv_bfloat16* __restrict__ wtHi,
    const __nv_bfloat16* __restrict__ wtLo,
    const float* __restrict__ bias,
    const float* __restrict__ bnw, const float* __restrict__ bnb,
    float* __restrict__ outf,
    __nv_bfloat16* __restrict__ oh, __nv_bfloat16* __restrict__ ol)
{
    extern __shared__ char smc[];
    const uint32_t s0 = smem_u32(smc);
    uint32_t* sAh = (uint32_t*)(smc + OFF_AH);
    uint32_t* sAl = (uint32_t*)(smc + OFF_AL);
    uint32_t* sBh = (uint32_t*)(smc + OFF_BH);
    uint32_t* sBl = (uint32_t*)(smc + OFF_BL);
    int2*     edg = (int2*)(smc + OFF_EDG);
    int*      ptr = (int*)(smc + OFF_PTR);

    const int tid  = threadIdx.x;
    const int wid  = tid >> 5;
    const int lane = tid & 31;
    const int g    = lane >> 2;
    const int tig  = lane & 3;
    const int warpM = wid & 1;      // 0..1 (80 rows each)
    const int warpN = wid >> 1;     // 0..3 (32 cols each)
    const int b    = blockIdx.x;
    const size_t rowbase = (size_t)b * NN;

    // stage edge list once (covered by the first __syncthreads in the k-loop)
    for (int i = tid; i < ETOT; i += 256) edg[i] = g_edge[i];
    if (tid <= NN) ptr[tid] = g_ptr[tid];

    float acc[5][4][4];
#pragma unroll
    for (int mf = 0; mf < 5; mf++)
#pragma unroll
        for (int nf = 0; nf < 4; nf++)
#pragma unroll
            for (int q = 0; q < 4; q++) acc[mf][nf][q] = 0.0f;

    // ldmatrix lane-relative offsets
    const int aRow0 = warpM * 80 + (lane & 7) + ((lane >> 3) & 1) * 8;
    const uint32_t aKoff = ((lane >> 4) & 1) * 16;
    const int bRow0 = warpN * 32 + (lane & 7) + ((lane >> 4) & 1) * 8;
    const uint32_t bKoff = ((lane >> 3) & 1) * 16;
    uint32_t aRel[5], bRel[2];
#pragma unroll
    for (int mf = 0; mf < 5; mf++)
        aRel[mf] = (uint32_t)(aRow0 + mf * 16) * AWB + aKoff;
#pragma unroll
    for (int nfp = 0; nfp < 2; nfp++)
        bRel[nfp] = (uint32_t)(bRow0 + nfp * 16) * AWB + bKoff;

    const uint32_t* gh32 = (const uint32_t*)wtHi;
    const uint32_t* gl32 = (const uint32_t*)wtLo;

    // hoisted staging coords
    const int sa_kp = tid & 31, sa_m0 = tid >> 5;         // AG path
    const int sc_g  = tid & 7,  sc_m0 = tid >> 3;         // copy path (8x16B/row)

    for (int t = 0; t < nchunks; t++) {
        if (t) __syncthreads();

        // ---- stage A ----
        if (AG) {
            // fp32 -> bf16 hi/lo split: 160 rows x 32 packed words (128 B/row)
            const int kg = t * 64 + sa_kp * 2;
            const bool kin0 = kg < K, kin1 = kg + 1 < K;
#pragma unroll
            for (int p = 0; p < 20; p++) {
                int m = sa_m0 + p * 8;
                float v0 = 0.0f, v1 = 0.0f;
                if (m < NN) {
                    const float* ap = xA + (rowbase + m) * (size_t)K + kg;
                    v0 = kin0 ? ap[0] : 0.0f;
                    v1 = kin1 ? ap[1] : 0.0f;
                }
                float h0f = __bfloat162float(__float2bfloat16(v0));
                float h1f = __bfloat162float(__float2bfloat16(v1));
                sAh[m * AW + sa_kp] = bf16x2_pack(h0f, h1f);
                sAl[m * AW + sa_kp] = bf16x2_pack(v0 - h0f, v1 - h1f);
            }
        } else {
            // pure copy of pre-split H: 2 arrays x 160 rows x 8 uint4 (128 B/row)
#pragma unroll
            for (int p = 0; p < 10; p++) {
                int idx = tid + p * 256;      // 0..2559
                int arr = idx >= 1280;
                int rem = arr ? idx - 1280 : idx;
                int m = rem >> 3, gg = rem & 7;   // m 0..159, gg 0..7 (16B)
                uint4 v = make_uint4(0, 0, 0, 0);
                if (m < NN) {
                    const __nv_bfloat16* src = (arr ? aLo : aHi) +
                        (rowbase + m) * CH + t * 64;
                    v = *(const uint4*)((const char*)src + gg * 16);
                }
                uint32_t* dst = arr ? sAl : sAh;
                *(uint4*)((char*)(dst + m * AW) + gg * 16) = v;
            }
        }
        // ---- stage B ----
        const uint32_t* gh = gh32 + t * 4096;
        const uint32_t* gl = gl32 + t * 4096;
#pragma unroll
        for (int p = 0; p < 16; p++) {
            int idx = tid + p * 256;
            int n = idx >> 5, w = idx & 31;
            sBh[n * AW + w] = gh[n * 32 + w];
            sBl[n * AW + w] = gl[n * 32 + w];
        }
        __syncthreads();

        // ---- compute: 4 k16 steps ----
        const uint32_t sAH = s0 + OFF_AH, sAL = s0 + OFF_AL;
        const uint32_t sBH = s0 + OFF_BH, sBL = s0 + OFF_BL;
#pragma unroll
        for (int ks = 0; ks < 4; ks++) {
            const uint32_t kb = (uint32_t)ks * 32;
            uint32_t bh[2][4], bl[2][4];
#pragma unroll
            for (int nfp = 0; nfp < 2; nfp++) {
                ldsm_x4(bh[nfp], sBH + bRel[nfp] + kb);
                ldsm_x4(bl[nfp], sBL + bRel[nfp] + kb);
            }
#pragma unroll
            for (int mf = 0; mf < 5; mf++) {
                uint32_t ah[4], al[4];
                ldsm_x4(ah, sAH + aRel[mf] + kb);
                ldsm_x4(al, sAL + aRel[mf] + kb);
#pragma unroll
                for (int nfp = 0; nfp < 2; nfp++)
#pragma unroll
                    for (int h = 0; h < 2; h++) {
                        int nf = nfp * 2 + h;
                        uint32_t b0 = bh[nfp][h * 2], b1 = bh[nfp][h * 2 + 1];
                        uint32_t c0 = bl[nfp][h * 2], c1 = bl[nfp][h * 2 + 1];
                        mma16816(acc[mf][nf], ah, b0, b1);
                        mma16816(acc[mf][nf], ah, c0, c1);
                        mma16816(acc[mf][nf], al, b0, b1);
                    }
            }
        }
    }
    __syncthreads();   // all smem reads done; T overlays A/B

    // ---- epilogue: fragments -> smem T [156][132] fp32 ----
    float* T = (float*)(smc + OFF_T);
#pragma unroll
    for (int mf = 0; mf < 5; mf++) {
#pragma unroll
        for (int nf = 0; nf < 4; nf++) {
            int row = warpM * 80 + mf * 16 + g;
            int col = warpN * 32 + nf * 8 + tig * 2;
            if (row < NN)
                *(float2*)&T[row * 132 + col] =
                    make_float2(acc[mf][nf][0], acc[mf][nf][1]);
            if (row + 8 < NN)
                *(float2*)&T[(row + 8) * 132 + col] =
                    make_float2(acc[mf][nf][2], acc[mf][nf][3]);
        }
    }
    __syncthreads();

    // ---- aggregation: warp-per-row, lane = 4 channels, 4 independent chains -
    const float4* T4 = (const float4*)T;   // row stride 33 float4
    float4 bias4 = ((const float4*)bias)[lane];
    float4 bnw4 = make_float4(0, 0, 0, 0), bnb4 = make_float4(0, 0, 0, 0);
    if (!LAST) {
        bnw4 = ((const float4*)bnw)[lane];
        bnw4.x *= BN_INV_SQRT; bnw4.y *= BN_INV_SQRT;
        bnw4.z *= BN_INV_SQRT; bnw4.w *= BN_INV_SQRT;
        bnb4 = ((const float4*)bnb)[lane];
    }

    for (int n = wid; n < NN; n += 8) {
        int e = ptr[n];
        const int end = ptr[n + 1];
        float4 a0 = make_float4(0, 0, 0, 0);
        float4 a1 = make_float4(0, 0, 0, 0);
        float4 a2 = make_float4(0, 0, 0, 0);
        float4 a3 = make_float4(0, 0, 0, 0);
        for (; e + 3 < end; e += 4) {
            int2 e0 = edg[e],     e1 = edg[e + 1];
            int2 e2 = edg[e + 2], e3 = edg[e + 3];
            float4 t0 = T4[e0.x * 33 + lane];
            float4 t1 = T4[e1.x * 33 + lane];
            float4 t2 = T4[e2.x * 33 + lane];
            float4 t3 = T4[e3.x * 33 + lane];
            fma4(a0, t0, __int_as_float(e0.y));
            fma4(a1, t1, __int_as_float(e1.y));
            fma4(a2, t2, __int_as_float(e2.y));
            fma4(a3, t3, __int_as_float(e3.y));
        }
        if (e + 1 < end) {
            int2 e0 = edg[e], e1 = edg[e + 1];
            float4 t0 = T4[e0.x * 33 + lane];
            float4 t1 = T4[e1.x * 33 + lane];
            fma4(a0, t0, __int_as_float(e0.y));
            fma4(a1, t1, __int_as_float(e1.y));
            e += 2;
        }
        if (e < end) {
            int2 e0 = edg[e];
            float4 t0 = T4[e0.x * 33 + lane];
            fma4(a2, t0, __int_as_float(e0.y));
        }
        float4 v;
        v.x = (a0.x + a1.x) + (a2.x + a3.x) + bias4.x;
        v.y = (a0.y + a1.y) + (a2.y + a3.y) + bias4.y;
        v.z = (a0.z + a1.z) + (a2.z + a3.z) + bias4.z;
        v.w = (a0.w + a1.w) + (a2.w + a3.w) + bias4.w;
        const size_t ofs = (rowbase + n) * CH + lane * 4;
        if (LAST) {
            *(float4*)(outf + ofs) = v;
        } else {
            v.x = fmaxf(fmaf(v.x, bnw4.x, bnb4.x), 0.0f);
            v.y = fmaxf(fmaf(v.y, bnw4.y, bnb4.y), 0.0f);
            v.z = fmaxf(fmaf(v.z, bnw4.z, bnb4.z), 0.0f);
            v.w = fmaxf(fmaf(v.w, bnw4.w, bnb4.w), 0.0f);
            __nv_bfloat16 hx = __float2bfloat16(v.x);
            __nv_bfloat16 hy = __float2bfloat16(v.y);
            __nv_bfloat16 hz = __float2bfloat16(v.z);
            __nv_bfloat16 hw = __float2bfloat16(v.w);
            float fx = __bfloat162float(hx), fy = __bfloat162float(hy);
            float fz = __bfloat162float(hz), fw = __bfloat162float(hw);
            uint2 hv, lv;
            hv.x = ((uint32_t)__bfloat16_as_ushort(hy) << 16) |
                   __bfloat16_as_ushort(hx);
            hv.y = ((uint32_t)__bfloat16_as_ushort(hw) << 16) |
                   __bfloat16_as_ushort(hz);
            lv.x = bf16x2_pack(v.x - fx, v.y - fy);
            lv.y = bf16x2_pack(v.z - fz, v.w - fw);
            *(uint2*)(oh + ofs) = hv;
            *(uint2*)(ol + ofs) = lv;
        }
    }
}

// ---------------- launch ----------------------------------------------------
extern "C" void kernel_launch(void* const* d_in, const int* in_sizes, int n_in,
                              void* d_out, int out_size)
{
    const float* x    = (const float*)d_in[0];
    const void*  ei   = d_in[1];
    const float* W0   = (const float*)d_in[2];
    const float* b0   = (const float*)d_in[3];
    const float* bnw0 = (const float*)d_in[4];
    const float* bnb0 = (const float*)d_in[5];
    const float* W1   = (const float*)d_in[6];
    const float* b1   = (const float*)d_in[7];
    const float* bnw1 = (const float*)d_in[8];
    const float* bnb1 = (const float*)d_in[9];
    const float* W2   = (const float*)d_in[10];
    const float* b2   = (const float*)d_in[11];
    float*       out  = (float*)d_out;

    __nv_bfloat16 *hh, *hl, *wh, *wl;
    cudaGetSymbolAddress((void**)&hh, g_Hhi);
    cudaGetSymbolAddress((void**)&hl, g_Hlo);
    cudaGetSymbolAddress((void**)&wh, g_WtHi);
    cudaGetSymbolAddress((void**)&wl, g_WtLo);

    cudaFuncSetAttribute(fused_layer<true, false>,
                         cudaFuncAttributeMaxDynamicSharedMemorySize, SMEM_FUSED);
    cudaFuncSetAttribute(fused_layer<false, false>,
                         cudaFuncAttributeMaxDynamicSharedMemorySize, SMEM_FUSED);
    cudaFuncSetAttribute(fused_layer<false, true>,
                         cudaFuncAttributeMaxDynamicSharedMemorySize, SMEM_FUSED);

    // build x2 (idempotent) so ncu -s 5 -c 1 captures fused layer 2 (#6).
    build_kernel<<<1, 256>>>(ei);                                     // 1
    build_kernel<<<1, 256>>>(ei);                                     // 2
    wprep_kernel<<<(NSLOT * CHUNK_ELEMS + 511) / 512, 512>>>(W0, W1, W2); // 3

    // layer 0: x @ W0 -> agg -> H (bf16 hi/lo)
    fused_layer<true, false><<<BATCH, 256, SMEM_FUSED>>>(
        x, CIN, 5, nullptr, nullptr, wh, wl,
        b0, bnw0, bnb0, nullptr, hh, hl);                             // 4
    // layer 1: H @ W1 -> agg -> H
    fused_layer<false, false><<<BATCH, 256, SMEM_FUSED>>>(
        nullptr, CH, 2, hh, hl, wh + 5 * CHUNK_ELEMS, wl + 5 * CHUNK_ELEMS,
        b1, bnw1, bnb1, nullptr, hh, hl);                             // 5
    // layer 2: H @ W2 -> agg -> out (fp32)
    fused_layer<false, true><<<BATCH, 256, SMEM_FUSED>>>(
        nullptr, CH, 2, hh, hl, wh + 7 * CHUNK_ELEMS, wl + 7 * CHUNK_ELEMS,
        b2, nullptr, nullptr, out, nullptr, nullptr);                 // 6 <- ncu
}